// round 4
// baseline (speedup 1.0000x reference)
#include <cuda_runtime.h>
#include <stdint.h>

#define BB 4
#define NN 4096
#define DD 128
#define KK 2048
#define EPSV 1e-10f
#define RPB 4     // rows per gatherg block (double-buffered TMA pipeline)

// ---- scratch (no allocation allowed) ----
__device__ unsigned long long d_keys[BB * NN];   // 128 KB
__device__ int   d_idx[BB * KK];
__device__ float d_vals[BB * KK];

// output layout: g_new | new_h | idx (float32)
#define OFF_G 0
#define OFF_H ((size_t)BB * KK * KK)
#define OFF_I (OFF_H + (size_t)BB * KK * DD)

__device__ __forceinline__ unsigned smem_u32(const void* p) {
    unsigned a;
    asm("{ .reg .u64 t; cvta.to.shared.u64 t, %1; cvt.u32.u64 %0, t; }" : "=r"(a) : "l"(p));
    return a;
}

// ---------------------------------------------------------------------------
// Kernel 1: scores = sigmoid(h . w + b) packed into sortable u64 keys.
// key = (score_bits << 32) | (0xFFFFFFFF - node). 2 nodes per warp for ILP.
// ---------------------------------------------------------------------------
__global__ void scores_kernel(const float4* __restrict__ h,
                              const float4* __restrict__ w,
                              const float* __restrict__ bptr) {
    int gwarp = (blockIdx.x * blockDim.x + threadIdx.x) >> 5;   // 2 nodes each
    int lane  = threadIdx.x & 31;
    int n0 = gwarp * 2;
    if (n0 >= BB * NN) return;
    float4 wv = w[lane];
    float4 a = h[(size_t)n0 * (DD / 4) + lane];
    float4 c = h[(size_t)(n0 + 1) * (DD / 4) + lane];
    float s0 = a.x * wv.x + a.y * wv.y + a.z * wv.z + a.w * wv.w;
    float s1 = c.x * wv.x + c.y * wv.y + c.z * wv.z + c.w * wv.w;
    #pragma unroll
    for (int o = 16; o; o >>= 1) {
        s0 += __shfl_xor_sync(0xFFFFFFFFu, s0, o);
        s1 += __shfl_xor_sync(0xFFFFFFFFu, s1, o);
    }
    if (lane < 2) {
        int nd = n0 + lane;
        float x  = (lane ? s1 : s0) + bptr[0];
        float sc = 1.0f / (1.0f + expf(-x));
        unsigned int sb = __float_as_uint(sc);
        unsigned int node = (unsigned int)(nd & (NN - 1));
        d_keys[nd] = ((unsigned long long)sb << 32) |
                     (unsigned long long)(0xFFFFFFFFu - node);
    }
}

// ---------------------------------------------------------------------------
// Kernel 2: exact rank-by-count (keys unique). One thread per node,
// 1 warp/SMSP across the chip; inner loop is broadcast LDS.128.
// ---------------------------------------------------------------------------
__global__ void rank_kernel() {
    __shared__ __align__(16) unsigned long long sk[NN];   // 32 KB
    const int b   = blockIdx.x >> 5;
    const int blk = blockIdx.x & 31;
    const int tid = threadIdx.x;           // 128 threads
    for (int i = tid; i < NN; i += 128) sk[i] = d_keys[b * NN + i];
    __syncthreads();

    const int node = blk * 128 + tid;
    const unsigned long long my = sk[node];
    const ulonglong2* sk2 = (const ulonglong2*)sk;
    int r = 0;
    #pragma unroll 8
    for (int i = 0; i < NN / 2; i++) {
        ulonglong2 kk = sk2[i];
        r += (kk.x > my) + (kk.y > my);
    }
    if (r < KK) {
        d_idx [b * KK + r] = node;
        d_vals[b * KK + r] = __uint_as_float((unsigned int)(my >> 32));
    }
}

// ---------------------------------------------------------------------------
// Kernel 3: gathered adjacency + degree normalize, fused new_h + idx.
// RPB rows per block, double-buffered TMA (cp.async.bulk) so only the first
// row pays fill latency; consume of row r overlaps DRAM fetch of row r+1.
// ---------------------------------------------------------------------------
__global__ void __launch_bounds__(256) gatherg_kernel(const float* __restrict__ g,
                                                      const float* __restrict__ h,
                                                      float* __restrict__ out) {
    __shared__ __align__(16) float buf[2][NN];              // 32 KB
    __shared__ float wsum[8];
    __shared__ __align__(8) unsigned long long bars[2];

    const int b    = blockIdx.y;
    const int base = blockIdx.x * RPB;
    const int tid  = threadIdx.x;

    const unsigned s_b0  = smem_u32(buf[0]);
    const unsigned s_b1  = smem_u32(buf[1]);
    const unsigned s_bar0 = smem_u32(&bars[0]);
    const unsigned s_bar1 = smem_u32(&bars[1]);

    if (tid == 0) {
        asm volatile("mbarrier.init.shared.b64 [%0], 1;" :: "r"(s_bar0) : "memory");
        asm volatile("mbarrier.init.shared.b64 [%0], 1;" :: "r"(s_bar1) : "memory");
        asm volatile("fence.proxy.async.shared::cta;" ::: "memory");
        // prime the pipeline: rows base+0 -> buf0, base+1 -> buf1
        #pragma unroll
        for (int s = 0; s < 2; s++) {
            const int node = d_idx[b * KK + base + s];
            const float* grow = g + ((size_t)b * NN + node) * NN;
            unsigned bar = s ? s_bar1 : s_bar0;
            unsigned dst = s ? s_b1 : s_b0;
            asm volatile("mbarrier.arrive.expect_tx.shared.b64 _, [%0], %1;"
                         :: "r"(bar), "r"(NN * 4) : "memory");
            asm volatile(
                "cp.async.bulk.shared::cluster.global.mbarrier::complete_tx::bytes "
                "[%0], [%1], %2, [%3];"
                :: "r"(dst), "l"(grow), "r"(NN * 4), "r"(bar) : "memory");
        }
    }

    // column indices for this batch (L2-hot), 8 consecutive j per thread
    const int4* cp4 = (const int4*)(d_idx + b * KK);
    const int4 c0 = cp4[tid * 2];
    const int4 c1 = cp4[tid * 2 + 1];
    __syncthreads();   // barriers initialized + primed

    for (int r = 0; r < RPB; r++) {
        const int   st   = r & 1;
        const unsigned parity = (r >> 1) & 1;
        const unsigned bar = st ? s_bar1 : s_bar0;
        const int   row  = b * KK + base + r;
        const int   node = d_idx[row];
        const float v    = d_vals[row];

        // fused new_h + idx while TMA may still be in flight
        if (tid < 32) {
            float4 hv = ((const float4*)(h + ((size_t)b * NN + node) * DD))[tid];
            hv.x *= v; hv.y *= v; hv.z *= v; hv.w *= v;
            ((float4*)(out + OFF_H + (size_t)row * DD))[tid] = hv;
        }
        if (tid == 32) out[OFF_I + row] = (float)node;

        // wait for this row's buffer
        unsigned done;
        do {
            asm volatile(
                "{ .reg .pred p; "
                "mbarrier.try_wait.parity.acquire.cta.shared::cta.b64 p, [%1], %2, 0x989680; "
                "selp.b32 %0, 1, 0, p; }"
                : "=r"(done) : "r"(bar), "r"(parity) : "memory");
        } while (!done);

        const float* srow = buf[st];
        float vv[8];
        vv[0] = srow[c0.x]; vv[1] = srow[c0.y]; vv[2] = srow[c0.z]; vv[3] = srow[c0.w];
        vv[4] = srow[c1.x]; vv[5] = srow[c1.y]; vv[6] = srow[c1.z]; vv[7] = srow[c1.w];
        float local = (vv[0] + vv[1]) + (vv[2] + vv[3]) +
                      ((vv[4] + vv[5]) + (vv[6] + vv[7]));
        #pragma unroll
        for (int o = 16; o; o >>= 1) local += __shfl_xor_sync(0xFFFFFFFFu, local, o);
        if ((tid & 31) == 0) wsum[tid >> 5] = local;
        __syncthreads();

        float deg = 0.f;
        #pragma unroll
        for (int wv = 0; wv < 8; wv++) deg += wsum[wv];
        const float inv = 1.0f / (deg + EPSV);

        float4* dst4 = (float4*)(out + OFF_G + (size_t)row * KK);
        dst4[tid * 2]     = make_float4(vv[0] * inv, vv[1] * inv, vv[2] * inv, vv[3] * inv);
        dst4[tid * 2 + 1] = make_float4(vv[4] * inv, vv[5] * inv, vv[6] * inv, vv[7] * inv);

        __syncthreads();   // everyone done with buf[st] and wsum
        if (tid == 0 && r + 2 < RPB) {
            const int nnode = d_idx[b * KK + base + r + 2];
            const float* grow = g + ((size_t)b * NN + nnode) * NN;
            unsigned dst = st ? s_b1 : s_b0;
            asm volatile("mbarrier.arrive.expect_tx.shared.b64 _, [%0], %1;"
                         :: "r"(bar), "r"(NN * 4) : "memory");
            asm volatile(
                "cp.async.bulk.shared::cluster.global.mbarrier::complete_tx::bytes "
                "[%0], [%1], %2, [%3];"
                :: "r"(dst), "l"(grow), "r"(NN * 4), "r"(bar) : "memory");
        }
    }
}

// ---------------------------------------------------------------------------
extern "C" void kernel_launch(void* const* d_in, const int* in_sizes, int n_in,
                              void* d_out, int out_size) {
    const float* g = (const float*)d_in[0];   // [B,N,N]
    const float* h = (const float*)d_in[1];   // [B,N,D]
    const float* w = (const float*)d_in[2];   // [D]
    const float* b = (const float*)d_in[3];   // scalar
    float* out = (float*)d_out;

    scores_kernel<<<(BB * NN) / 8, 128>>>((const float4*)h, (const float4*)w, b);
    rank_kernel<<<BB * 32, 128>>>();
    dim3 grid(KK / RPB, BB);
    gatherg_kernel<<<grid, 256>>>(g, h, out);
}

// round 5
// speedup vs baseline: 1.0902x; 1.0902x over previous
#include <cuda_runtime.h>
#include <stdint.h>

#define BB 4
#define NN 4096
#define DD 128
#define KK 2048
#define EPSV 1e-10f
#define RPB 4     // rows per gatherg block

// ---- scratch (no allocation allowed) ----
__device__ unsigned long long d_keys[BB * NN];   // 128 KB
__device__ int   d_idx[BB * KK];
__device__ float d_vals[BB * KK];

// output layout: g_new | new_h | idx (float32)
#define OFF_G 0
#define OFF_H ((size_t)BB * KK * KK)
#define OFF_I (OFF_H + (size_t)BB * KK * DD)

__device__ __forceinline__ unsigned smem_u32(const void* p) {
    unsigned a;
    asm("{ .reg .u64 t; cvta.to.shared.u64 t, %1; cvt.u32.u64 %0, t; }" : "=r"(a) : "l"(p));
    return a;
}

// ---------------------------------------------------------------------------
// Kernel 1: scores = sigmoid(h . w + b) packed into sortable u64 keys.
// key = (score_bits << 32) | (0xFFFFFFFF - node). 4 nodes per warp for MLP.
// ---------------------------------------------------------------------------
__global__ void scores_kernel(const float4* __restrict__ h,
                              const float4* __restrict__ w,
                              const float* __restrict__ bptr) {
    int gwarp = (blockIdx.x * blockDim.x + threadIdx.x) >> 5;
    int lane  = threadIdx.x & 31;
    int n0 = gwarp * 4;
    if (n0 >= BB * NN) return;
    float4 wv = w[lane];
    float s[4];
    #pragma unroll
    for (int u = 0; u < 4; u++) {
        float4 a = h[(size_t)(n0 + u) * (DD / 4) + lane];
        s[u] = a.x * wv.x + a.y * wv.y + a.z * wv.z + a.w * wv.w;
    }
    #pragma unroll
    for (int o = 16; o; o >>= 1) {
        #pragma unroll
        for (int u = 0; u < 4; u++) s[u] += __shfl_xor_sync(0xFFFFFFFFu, s[u], o);
    }
    if (lane < 4) {
        int nd = n0 + lane;
        float x  = s[lane] + bptr[0];
        float sc = 1.0f / (1.0f + expf(-x));
        unsigned int sb = __float_as_uint(sc);
        unsigned int node = (unsigned int)(nd & (NN - 1));
        d_keys[nd] = ((unsigned long long)sb << 32) |
                     (unsigned long long)(0xFFFFFFFFu - node);
    }
}

// ---------------------------------------------------------------------------
// Kernel 2: exact rank-by-count (keys unique). 256 threads / 128 nodes per
// block: each node's 4096 compares split across 2 threads, combined in smem.
// ---------------------------------------------------------------------------
__global__ void rank_kernel() {
    __shared__ __align__(16) unsigned long long sk[NN];   // 32 KB
    __shared__ int part[128];
    const int b   = blockIdx.x >> 5;
    const int blk = blockIdx.x & 31;
    const int tid = threadIdx.x;           // 256 threads
    for (int i = tid; i < NN; i += 256) sk[i] = d_keys[b * NN + i];
    __syncthreads();

    const int node = blk * 128 + (tid & 127);
    const int half = tid >> 7;
    const unsigned long long my = sk[node];
    const ulonglong2* sk2 = (const ulonglong2*)(sk + half * (NN / 2));
    int r = 0;
    #pragma unroll 8
    for (int i = 0; i < NN / 4; i++) {
        ulonglong2 kk = sk2[i];
        r += (kk.x > my) + (kk.y > my);
    }
    if (half) part[tid & 127] = r;
    __syncthreads();
    if (!half) {
        r += part[tid];
        if (r < KK) {
            d_idx [b * KK + r] = node;
            d_vals[b * KK + r] = __uint_as_float((unsigned int)(my >> 32));
        }
    }
}

// ---------------------------------------------------------------------------
// Kernel 3: gathered adjacency + degree normalize, fused new_h + idx.
// Per-thread cp.async staging (parallel issue, zero register pressure),
// 2-buffer lookahead via cp.async.wait_group. Next row's copy is issued
// BEFORE the current row's output stores, overlapping read & write phases.
// ---------------------------------------------------------------------------
__global__ void __launch_bounds__(256) gatherg_kernel(const float* __restrict__ g,
                                                      const float* __restrict__ h,
                                                      float* __restrict__ out) {
    __shared__ __align__(16) float buf[2][NN];              // 32 KB
    __shared__ float wsum[8];

    const int b    = blockIdx.y;
    const int base = blockIdx.x * RPB;
    const int tid  = threadIdx.x;

    // issue one row's 16KB as 4x16B cp.async per thread
    auto issue_row = [&](int r, int st) {
        const int node = d_idx[b * KK + base + r];
        const char* gsrc = (const char*)(g + ((size_t)b * NN + node) * NN) + tid * 16;
        unsigned sdst = smem_u32(buf[st]) + tid * 16;
        #pragma unroll
        for (int c = 0; c < 4; c++) {
            asm volatile("cp.async.cg.shared.global [%0], [%1], 16;"
                         :: "r"(sdst + c * 4096), "l"(gsrc + c * 4096) : "memory");
        }
        asm volatile("cp.async.commit_group;" ::: "memory");
    };

    issue_row(0, 0);
    issue_row(1, 1);

    // column indices for this batch (L2-hot), 8 consecutive j per thread,
    // reused for all RPB rows
    const int4* cp4 = (const int4*)(d_idx + b * KK);
    const int4 c0 = cp4[tid * 2];
    const int4 c1 = cp4[tid * 2 + 1];

    #pragma unroll
    for (int r = 0; r < RPB; r++) {
        const int   st   = r & 1;
        const int   row  = b * KK + base + r;
        const int   node = d_idx[row];
        const float v    = d_vals[row];

        // fused new_h + idx (independent of buf; overlaps pending copies)
        if (tid < 32) {
            float4 hv = ((const float4*)(h + ((size_t)b * NN + node) * DD))[tid];
            hv.x *= v; hv.y *= v; hv.z *= v; hv.w *= v;
            ((float4*)(out + OFF_H + (size_t)row * DD))[tid] = hv;
        }
        if (tid == 32) out[OFF_I + row] = (float)node;

        // wait for row r's buffer: 1 newer group may stay pending, except last
        if (r < RPB - 1)
            asm volatile("cp.async.wait_group 1;" ::: "memory");
        else
            asm volatile("cp.async.wait_group 0;" ::: "memory");
        __syncthreads();

        const float* srow = buf[st];
        float vv[8];
        vv[0] = srow[c0.x]; vv[1] = srow[c0.y]; vv[2] = srow[c0.z]; vv[3] = srow[c0.w];
        vv[4] = srow[c1.x]; vv[5] = srow[c1.y]; vv[6] = srow[c1.z]; vv[7] = srow[c1.w];
        float local = (vv[0] + vv[1]) + (vv[2] + vv[3]) +
                      ((vv[4] + vv[5]) + (vv[6] + vv[7]));
        #pragma unroll
        for (int o = 16; o; o >>= 1) local += __shfl_xor_sync(0xFFFFFFFFu, local, o);
        if ((tid & 31) == 0) wsum[tid >> 5] = local;
        __syncthreads();   // all LDS of buf[st] complete; wsum visible

        float deg = 0.f;
        #pragma unroll
        for (int wv = 0; wv < 8; wv++) deg += wsum[wv];
        const float inv = 1.0f / (deg + EPSV);

        // buf[st] is now free: start the next fetch BEFORE the writes
        if (r + 2 < RPB) issue_row(r + 2, st);

        float4* dst4 = (float4*)(out + OFF_G + (size_t)row * KK);
        dst4[tid * 2]     = make_float4(vv[0] * inv, vv[1] * inv, vv[2] * inv, vv[3] * inv);
        dst4[tid * 2 + 1] = make_float4(vv[4] * inv, vv[5] * inv, vv[6] * inv, vv[7] * inv);
    }
}

// ---------------------------------------------------------------------------
extern "C" void kernel_launch(void* const* d_in, const int* in_sizes, int n_in,
                              void* d_out, int out_size) {
    const float* g = (const float*)d_in[0];   // [B,N,N]
    const float* h = (const float*)d_in[1];   // [B,N,D]
    const float* w = (const float*)d_in[2];   // [D]
    const float* b = (const float*)d_in[3];   // scalar
    float* out = (float*)d_out;

    scores_kernel<<<(BB * NN) / 16, 128>>>((const float4*)h, (const float4*)w, b);
    rank_kernel<<<BB * 32, 256>>>();
    dim3 grid(KK / RPB, BB);
    gatherg_kernel<<<grid, 256>>>(g, h, out);
}